// round 2
// baseline (speedup 1.0000x reference)
#include <cuda_runtime.h>

#define T_STEPS 15
#define C_IN    6
#define HW      256
#define NPIX    65536            // 256*256
#define C_OUT   64
#define THRESH  15.0f
#define NELEM   62914560         // 15*64*256*256

// small per-pixel maps (device globals; no allocation)
__device__ float         g_max [T_STEPS * NPIX];   // max over channels of thresholded pot, per (t,pixel)
__device__ unsigned char g_amax[T_STEPS * NPIX];   // argmax channel per (t,pixel)
__device__ int           g_winfo[NPIX];            // -1 = no spike; else winner_c | (count<<8)
__device__ float         g_firstpot[NPIX];         // pot(te, winner) (0 if none)

// ---------------------------------------------------------------------------
// K1: 5x5 conv (6->64) for one time step over a 32x8 pixel tile, fused
// threshold, writes thr_pot into the `pot` output region, and reduces
// per-pixel max/argmax over the 64 channels into g_max/g_amax.
// Accumulation: ONE sequential fp32 FMA chain per output, in (ky, kx, c_in)
// order (c_in fastest) to match cuDNN-NHWC / Eigen patch ordering.
// ---------------------------------------------------------------------------
__global__ __launch_bounds__(256) void conv_kernel(const float* __restrict__ in,
                                                   const float* __restrict__ wg,
                                                   float* __restrict__ pot)
{
    __shared__ float ws[C_OUT * 150];      // 38400 B, laid out [c][ky][kx][i]
    __shared__ float xs[C_IN * 12 * 36];   // 10368 B   (total 48768 B < 48KB)

    const int t   = blockIdx.z;
    const int x0  = blockIdx.x * 32;
    const int y0  = blockIdx.y * 8;
    const int tid = threadIdx.x;

    // load weights, transposing OIHW -> [c][(ky*5+kx)*6 + i]
    for (int k = tid; k < C_OUT * 150; k += 256) {
        const int c = k / 150, q = k % 150;
        const int i = q / 25, r = q % 25;
        const int ky = r / 5, kx = r % 5;
        ws[c * 150 + (ky * 5 + kx) * 6 + i] = wg[k];
    }

    const float* inT = in + (size_t)t * C_IN * NPIX;
    for (int k = tid; k < C_IN * 12 * 36; k += 256) {
        int i  = k / (12 * 36);
        int r  = k % (12 * 36);
        int hy = r / 36, hx = r % 36;
        int gy = y0 + hy - 2, gx = x0 + hx - 2;
        float v = 0.f;
        if (gy >= 0 && gy < HW && gx >= 0 && gx < HW)
            v = inT[i * NPIX + gy * HW + gx];
        xs[k] = v;
    }
    __syncthreads();

    const int lw = tid & 31;
    const int cg = tid >> 5;

    float acc[8][8];
#pragma unroll
    for (int h = 0; h < 8; h++)
#pragma unroll
        for (int j = 0; j < 8; j++) acc[h][j] = 0.f;

    // strict sequential chain per output, order (ky, kx, i)
    for (int ky = 0; ky < 5; ky++) {
#pragma unroll
        for (int kx = 0; kx < 5; kx++) {
#pragma unroll
            for (int i = 0; i < C_IN; i++) {
                const int q = (ky * 5 + kx) * 6 + i;
                float wv[8], xv[8];
#pragma unroll
                for (int j = 0; j < 8; j++) wv[j] = ws[(cg * 8 + j) * 150 + q];
#pragma unroll
                for (int h = 0; h < 8; h++) xv[h] = xs[(i * 12 + ky + h) * 36 + lw + kx];
#pragma unroll
                for (int h = 0; h < 8; h++)
#pragma unroll
                    for (int j = 0; j < 8; j++)
                        acc[h][j] = fmaf(xv[h], wv[j], acc[h][j]);
            }
        }
    }
    __syncthreads();   // done with ws/xs contents; reuse ws region for reduction

    float* redv = ws;                    // [cg*8+h][lw] : 2048 floats
    int*   redi = (int*)(ws + 2048);     // same layout  : 2048 ints

#pragma unroll
    for (int h = 0; h < 8; h++) {
        float bv = -1.f;
        int   bc = 0;
        const size_t rowbase = (((size_t)t * C_OUT) * HW + (size_t)(y0 + h)) * HW + x0 + lw;
#pragma unroll
        for (int j = 0; j < 8; j++) {
            const int c = cg * 8 + j;
            float v = acc[h][j];
            v = (v >= THRESH) ? v : 0.f;                 // sf.fire threshold
            pot[rowbase + (size_t)c * NPIX] = v;         // thr_pot staged in output
            if (v > bv) { bv = v; bc = c; }              // strict > : lowest c wins ties
        }
        redv[(cg * 8 + h) * 32 + lw] = bv;
        redi[(cg * 8 + h) * 32 + lw] = bc;
    }
    __syncthreads();

    for (int s = 4; s >= 1; s >>= 1) {
        if (cg < s) {
#pragma unroll
            for (int h = 0; h < 8; h++) {
                const int a = (cg * 8 + h) * 32 + lw;
                const int b = ((cg + s) * 8 + h) * 32 + lw;
                const float vL = redv[a], vR = redv[b];
                if (vR > vL) { redv[a] = vR; redi[a] = redi[b]; }  // ties keep left (lower c)
            }
        }
        __syncthreads();
    }

    if (cg == 0) {
#pragma unroll
        for (int h = 0; h < 8; h++) {
            const int pix = (y0 + h) * HW + x0 + lw;
            g_max [t * NPIX + pix] = redv[h * 32 + lw];
            g_amax[t * NPIX + pix] = (unsigned char)redi[h * 32 + lw];
        }
    }
}

// ---------------------------------------------------------------------------
// K2: per pixel, find earliest firing time te (spikes are cumulative so the
// first t with any channel above threshold). winner = argmax channel at te.
// count = 15 - te. Encode in g_winfo / g_firstpot.
// ---------------------------------------------------------------------------
__global__ void winner_kernel()
{
    const int p = blockIdx.x * blockDim.x + threadIdx.x;
    if (p >= NPIX) return;
    int   info = -1;
    float fp   = 0.f;
    for (int t = 0; t < T_STEPS; t++) {
        const float m = g_max[t * NPIX + p];
        if (m > 0.f) {
            info = (int)g_amax[t * NPIX + p] | ((T_STEPS - t) << 8);
            fp   = m;
            break;
        }
    }
    g_winfo[p]    = info;
    g_firstpot[p] = fp;
}

// ---------------------------------------------------------------------------
// K3: pointwise inhibition materialization. For every output element, keep
// the staged thr_pot value only at the winner channel; emit spk = sign(pot).
// In-place rewrite of the pot region; float4 stores.
// ---------------------------------------------------------------------------
__global__ __launch_bounds__(256) void emit_kernel(float* __restrict__ spk,
                                                   float* __restrict__ pot)
{
    const size_t u = (size_t)blockIdx.x * 256 + threadIdx.x; // over NELEM/4 units
    const int w4 = (int)(u & 63);
    size_t r = u >> 6;
    const int h = (int)(r & 255); r >>= 8;
    const int c = (int)(r & 63);
    const int t = (int)(r >> 6);

    const int pix = (h << 8) | (w4 << 2);
    const int4 wi = *reinterpret_cast<const int4*>(g_winfo + pix);
    const size_t e = ((size_t)t * C_OUT + (size_t)c) * NPIX + (size_t)pix;

    float4 pv, sv;
    float v;
    v = (wi.x >= 0 && (wi.x & 255) == c) ? pot[e + 0] : 0.f; pv.x = v; sv.x = (v > 0.f) ? 1.f : 0.f;
    v = (wi.y >= 0 && (wi.y & 255) == c) ? pot[e + 1] : 0.f; pv.y = v; sv.y = (v > 0.f) ? 1.f : 0.f;
    v = (wi.z >= 0 && (wi.z & 255) == c) ? pot[e + 2] : 0.f; pv.z = v; sv.z = (v > 0.f) ? 1.f : 0.f;
    v = (wi.w >= 0 && (wi.w & 255) == c) ? pot[e + 3] : 0.f; pv.w = v; sv.w = (v > 0.f) ? 1.f : 0.f;

    *reinterpret_cast<float4*>(pot + e) = pv;
    *reinterpret_cast<float4*>(spk + e) = sv;
}

// ---------------------------------------------------------------------------
// K4: get_k_winners. total(pixel) = count*(firstpot + v), v = 15*max(firstpot).
// 5 greedy rounds of global argmax with feature-plane ban (winner channel)
// and 7x7 spatial box ban. Ties broken by flat (c,h,w) index like jnp.argmax.
// Single block, two-phase.
// ---------------------------------------------------------------------------
__global__ __launch_bounds__(1024) void kwta_kernel(float* __restrict__ owin)
{
    __shared__ float sv_[1024];
    __shared__ int   si_[1024];
    __shared__ float s_v;
    __shared__ int   bc_[5], bh_[5], bw_[5];

    const int tid = threadIdx.x;

    float m = 0.f;
    for (int p = tid; p < NPIX; p += 1024) m = fmaxf(m, g_firstpot[p]);
    sv_[tid] = m;
    __syncthreads();
    for (int s = 512; s >= 1; s >>= 1) {
        if (tid < s) sv_[tid] = fmaxf(sv_[tid], sv_[tid + s]);
        __syncthreads();
    }
    if (tid == 0) s_v = sv_[0] * (float)T_STEPS;
    __syncthreads();
    const float v = s_v;

    for (int round = 0; round < 5; round++) {
        float bv = 0.f;
        int   bk = 0x7fffffff;
        for (int p = tid; p < NPIX; p += 1024) {
            const int info = g_winfo[p];
            if (info < 0) continue;
            const int wc = info & 255;
            const int h = p >> 8, w = p & 255;
            bool ban = false;
            for (int b = 0; b < round; b++) {
                if (bc_[b] == wc) ban = true;
                if (h >= bh_[b] - 3 && h <= bh_[b] + 3 &&
                    w >= bw_[b] - 3 && w <= bw_[b] + 3) ban = true;
            }
            if (ban) continue;
            const float tot = (float)(info >> 8) * (g_firstpot[p] + v);
            const int flat = (wc << 16) | p;
            if (tot > bv || (tot == bv && flat < bk)) { bv = tot; bk = flat; }
        }
        sv_[tid] = bv; si_[tid] = bk;
        __syncthreads();
        for (int s = 512; s >= 1; s >>= 1) {
            if (tid < s) {
                const float vR = sv_[tid + s];
                if (vR > sv_[tid] || (vR == sv_[tid] && si_[tid + s] < si_[tid])) {
                    sv_[tid] = vR; si_[tid] = si_[tid + s];
                }
            }
            __syncthreads();
        }
        if (tid == 0) {
            if (sv_[0] > 0.f) {
                const int flat = si_[0];
                const int c = flat >> 16, h = (flat >> 8) & 255, w = flat & 255;
                owin[round * 3 + 0] = (float)c;
                owin[round * 3 + 1] = (float)h;
                owin[round * 3 + 2] = (float)w;
                bc_[round] = c; bh_[round] = h; bw_[round] = w;
            } else {
                owin[round * 3 + 0] = -1.f;
                owin[round * 3 + 1] = -1.f;
                owin[round * 3 + 2] = -1.f;
                bc_[round] = -1; bh_[round] = -100000; bw_[round] = -100000;
            }
        }
        __syncthreads();
    }
}

// ---------------------------------------------------------------------------
extern "C" void kernel_launch(void* const* d_in, const int* in_sizes, int n_in,
                              void* d_out, int out_size)
{
    (void)in_sizes; (void)n_in; (void)out_size;
    const float* in = (const float*)d_in[0];
    const float* w1 = (const float*)d_in[1];

    float* out = (float*)d_out;
    float* spk = out;
    float* pot = out + (size_t)NELEM;
    float* win = out + (size_t)2 * NELEM;

    conv_kernel<<<dim3(8, 32, 15), 256>>>(in, w1, pot);
    winner_kernel<<<NPIX / 256, 256>>>();
    emit_kernel<<<NELEM / 4 / 256, 256>>>(spk, pot);
    kwta_kernel<<<1, 1024>>>(win);
}